// round 3
// baseline (speedup 1.0000x reference)
#include <cuda_runtime.h>
#include <math_constants.h>

// Problem shape (fixed by the dataset):
// x: (4, 128, 31, 32, 22) f32; w1,w2: (128,); b1,b2 scalars; top_k = 16
// out: (4, 16, 30, 32, 22) f32
#define NB   4
#define CC   128
#define SSZ  31
#define HW   704      // 32*22
#define SM1  30       // SSZ-1
#define NP   (NB*SM1) // 120 frame pairs
#define KK   16
#define LOG2E 1.4426950408889634f

// Scratch (allocation-free rule: __device__ globals)
__device__ float g_Y1[NB*SSZ*HW];   // dot(x, w1) per pixel, no bias
__device__ float g_Y2[NB*SSZ*HW];   // dot(x, w2) per pixel, no bias
__device__ float g_sel[NP*32];      // per pair: [0..15] top16 of u desc, [16..31] bot16 asc (u = (Y2+b2)*log2e)

__device__ __forceinline__ float ex2f(float x) {
    float y;
    asm("ex2.approx.ftz.f32 %0, %1;" : "=f"(y) : "f"(x));
    return y;
}

// ---------------------------------------------------------------------------
// Kernel A: 1x1 conv (C->1) for both weight vectors in one pass over x (45 MB)
// ---------------------------------------------------------------------------
__global__ __launch_bounds__(256)
void conv_kernel(const float* __restrict__ x,
                 const float* __restrict__ w1,
                 const float* __restrict__ w2) {
    int t = blockIdx.x * blockDim.x + threadIdx.x;  // pixel id over (n, s, hw)
    if (t >= NB*SSZ*HW) return;
    int i  = t % HW;
    int rs = t / HW;          // n*SSZ + s
    int n  = rs / SSZ;
    int s  = rs % SSZ;
    const float* xp = x + (((size_t)n*CC)*SSZ + s)*HW + i;
    float a1 = 0.f, a2 = 0.f;
    #pragma unroll 8
    for (int c = 0; c < CC; ++c) {
        float v = xp[(size_t)c * (SSZ*HW)];
        a1 = fmaf(v, __ldg(&w1[c]), a1);
        a2 = fmaf(v, __ldg(&w2[c]), a2);
    }
    g_Y1[t] = a1;
    g_Y2[t] = a2;
}

// ---------------------------------------------------------------------------
// Kernel C: per pair, select top16 (desc) and bottom16 (asc) of
//           u_j = (Y2[n, s+1, j] + b2) * log2e
// ---------------------------------------------------------------------------
__global__ __launch_bounds__(256)
void sel_kernel(const float* __restrict__ b2p) {
    __shared__ float w[HW];
    __shared__ float rv[256];
    __shared__ int   ri[256];
    __shared__ float sel[32];
    const int p = blockIdx.x;
    const int n = p / SM1, s = p % SM1;
    const int tid = threadIdx.x;
    const float b2 = *b2p;

    for (int j = tid; j < HW; j += 256)
        w[j] = (g_Y2[(n*SSZ + s + 1)*HW + j] + b2) * LOG2E;
    __syncthreads();

    // 16 iterative argmax passes (destructive)
    for (int k = 0; k < KK; ++k) {
        float bv = -CUDART_INF_F; int bi = 0;
        for (int j = tid; j < HW; j += 256)
            if (w[j] > bv) { bv = w[j]; bi = j; }
        rv[tid] = bv; ri[tid] = bi; __syncthreads();
        for (int st = 128; st > 0; st >>= 1) {
            if (tid < st && rv[tid+st] > rv[tid]) { rv[tid] = rv[tid+st]; ri[tid] = ri[tid+st]; }
            __syncthreads();
        }
        if (tid == 0) { sel[k] = rv[0]; w[ri[0]] = -CUDART_INF_F; }
        __syncthreads();
    }
    // reload and do 16 argmin passes
    for (int j = tid; j < HW; j += 256)
        w[j] = (g_Y2[(n*SSZ + s + 1)*HW + j] + b2) * LOG2E;
    __syncthreads();
    for (int k = 0; k < KK; ++k) {
        float bv = CUDART_INF_F; int bi = 0;
        for (int j = tid; j < HW; j += 256)
            if (w[j] < bv) { bv = w[j]; bi = j; }
        rv[tid] = bv; ri[tid] = bi; __syncthreads();
        for (int st = 128; st > 0; st >>= 1) {
            if (tid < st && rv[tid+st] < rv[tid]) { rv[tid] = rv[tid+st]; ri[tid] = ri[tid+st]; }
            __syncthreads();
        }
        if (tid == 0) { sel[KK + k] = rv[0]; w[ri[0]] = CUDART_INF_F; }
        __syncthreads();
    }
    if (tid < 32) g_sel[p*32 + tid] = sel[tid];
}

// ---------------------------------------------------------------------------
// Kernel B: per-row partition sums + top-k softmax values.
// One lane owns one row i: a = Y1[n,s,i]+b1; S = sum_j exp2(a*u_j - m2).
// Output mapping (torch .view semantics): within a pair, output flat index
// L = kq*704 + j holds val(row = L>>4, rank = L&15). Row i's 16 rank-values
// therefore occupy the contiguous range L in [16i, 16i+16); since 704 = 44*16
// this range never crosses a kq-slice boundary: kq = i/44, j0 = (16i) % 704.
// grid = NP*11 blocks, 64 threads (each block covers 64 consecutive rows).
// ---------------------------------------------------------------------------
__global__ __launch_bounds__(64)
void attn_kernel(const float* __restrict__ b1p,
                 const float* __restrict__ b2p,
                 float* __restrict__ out) {
    __shared__ float4 u4[HW/4];
    __shared__ float  selU[32];
    const int blk   = blockIdx.x;
    const int p     = blk / 11;
    const int chunk = blk % 11;           // 64-row chunk within the pair
    const int n = p / SM1, s = p % SM1;
    const int tid = threadIdx.x;
    const float b1 = *b1p, b2 = *b2p;

    float* u = reinterpret_cast<float*>(u4);
    for (int j = tid; j < HW; j += 64)
        u[j] = (g_Y2[(n*SSZ + s + 1)*HW + j] + b2) * LOG2E;
    if (tid < 32) selU[tid] = g_sel[p*32 + tid];
    __syncthreads();

    const float umax = selU[0], umin = selU[16];
    const int   i  = chunk*64 + tid;                  // row in [0, 704)
    const float a  = g_Y1[(n*SSZ + s)*HW + i] + b1;
    const bool  pos = (a > 0.f);
    const float m2 = a * (pos ? umax : umin);         // max logit in log2 domain

    float acc0 = 0.f, acc1 = 0.f, acc2 = 0.f, acc3 = 0.f;
    #pragma unroll 4
    for (int j = 0; j < HW/4; ++j) {
        float4 uu = u4[j];                            // broadcast LDS.128
        acc0 += ex2f(fmaf(a, uu.x, -m2));
        acc1 += ex2f(fmaf(a, uu.y, -m2));
        acc2 += ex2f(fmaf(a, uu.z, -m2));
        acc3 += ex2f(fmaf(a, uu.w, -m2));
    }
    const float inv = 1.0f / ((acc0 + acc1) + (acc2 + acc3));

    const float* selp = pos ? selU : (selU + KK);
    float vals[KK];
    #pragma unroll
    for (int k = 0; k < KK; ++k)
        vals[k] = ex2f(fmaf(a, selp[k], -m2)) * inv;

    // Output address for this row's 16 contiguous values.
    const int Lbase = i * KK;            // 16*i
    const int kq    = Lbase / HW;        // = i / 44
    const int j0    = Lbase % HW;
    float* op = out + (((size_t)(n*KK + kq))*SM1 + s)*HW + j0;
    float4* op4 = reinterpret_cast<float4*>(op);
    const float4* v4 = reinterpret_cast<const float4*>(vals);
    #pragma unroll
    for (int q = 0; q < 4; ++q)
        op4[q] = v4[q];
}

extern "C" void kernel_launch(void* const* d_in, const int* in_sizes, int n_in,
                              void* d_out, int out_size) {
    const float* x  = (const float*)d_in[0];
    const float* w1 = (const float*)d_in[1];
    const float* b1 = (const float*)d_in[2];
    const float* w2 = (const float*)d_in[3];
    const float* b2 = (const float*)d_in[4];
    float* out = (float*)d_out;

    const int npix = NB*SSZ*HW;                       // 87296
    conv_kernel<<<(npix + 255)/256, 256>>>(x, w1, w2);
    sel_kernel<<<NP, 256>>>(b2);
    attn_kernel<<<NP*11, 64>>>(b1, b2, out);
}

// round 4
// speedup vs baseline: 1.4355x; 1.4355x over previous
#include <cuda_runtime.h>
#include <math_constants.h>

// Problem shape (fixed by the dataset):
// x: (4, 128, 31, 32, 22) f32; w1,w2: (128,); b1,b2 scalars; top_k = 16
// out: (4, 16, 30, 32, 22) f32
#define NB   4
#define CC   128
#define SSZ  31
#define HW   704      // 32*22
#define SM1  30       // SSZ-1
#define NP   (NB*SM1) // 120 frame pairs
#define KK   16
#define NPIX (NB*SSZ*HW)   // 87296
#define FRM  (SSZ*HW)      // 21824 (elements per (n,c) slab row-block)
#define LOG2E 1.4426950408889634f

// Scratch (allocation-free rule: __device__ globals)
__device__ float g_Y1[NPIX];   // dot(x, w1) per pixel, no bias
__device__ float g_Y2[NPIX];   // dot(x, w2) per pixel, no bias
__device__ float g_sel[NP*32]; // per pair: [0..15] top16 of u desc, [16..31] bot16 asc

__device__ __forceinline__ float ex2f(float x) {
    float y;
    asm("ex2.approx.ftz.f32 %0, %1;" : "=f"(y) : "f"(x));
    return y;
}

// ---------------------------------------------------------------------------
// Kernel A: 1x1 conv (C->1) for both weight vectors, one pass over x (45 MB).
// 512 threads/block: 256 pixels, channel-split-2 (64 ch per thread),
// weights in smem, combine halves via smem. Goal: saturate HBM.
// ---------------------------------------------------------------------------
__global__ __launch_bounds__(512)
void conv_kernel(const float* __restrict__ x,
                 const float* __restrict__ w1,
                 const float* __restrict__ w2) {
    __shared__ float sw1[CC], sw2[CC];
    __shared__ float part1[256], part2[256];
    const int tid  = threadIdx.x;
    const int lane = tid & 255;
    const int half = tid >> 8;            // 0 or 1
    if (tid < CC) { sw1[tid] = w1[tid]; sw2[tid] = w2[tid]; }

    const int t = blockIdx.x * 256 + lane;        // flat pixel id (n, s, hw)
    const int n = t / FRM;
    // x addr for (n, c, s, i): c*FRM + t + n*(CC-1)*FRM
    const float* xp = x + (size_t)n * (CC - 1) * FRM + t + (size_t)half * 64 * FRM;
    const float* pw1 = sw1 + half * 64;
    const float* pw2 = sw2 + half * 64;
    __syncthreads();

    float a1 = 0.f, a2 = 0.f;
    #pragma unroll 16
    for (int c = 0; c < 64; ++c) {
        float v = xp[(size_t)c * FRM];
        a1 = fmaf(v, pw1[c], a1);
        a2 = fmaf(v, pw2[c], a2);
    }
    if (half) { part1[lane] = a1; part2[lane] = a2; }
    __syncthreads();
    if (!half) {
        g_Y1[t] = a1 + part1[lane];
        g_Y2[t] = a2 + part2[lane];
    }
}

// ---------------------------------------------------------------------------
// Kernel C: per pair, top16 (desc) and bottom16 (asc) of
//           u_j = (Y2[n, s+1, j] + b2) * log2e.
// Block = 64 threads: warp 0 -> top16, warp 1 -> bottom16. Register-resident
// values (22/lane), warp-shuffle argmax, ballot-elected single removal.
// ---------------------------------------------------------------------------
__global__ __launch_bounds__(64)
void sel_kernel(const float* __restrict__ b2p) {
    const int p    = blockIdx.x;
    const int n    = p / SM1, s = p % SM1;
    const int lane = threadIdx.x & 31;
    const int wid  = threadIdx.x >> 5;        // 0: max, 1: min
    const float b2 = *b2p;
    const float* Y2 = g_Y2 + (n*SSZ + s + 1)*HW;

    float v[22];
    #pragma unroll
    for (int q = 0; q < 22; ++q)
        v[q] = (Y2[q*32 + lane] + b2) * LOG2E;
    // min-warp negates: then both warps run identical max-selection.
    if (wid) {
        #pragma unroll
        for (int q = 0; q < 22; ++q) v[q] = -v[q];
    }

    float* outp = g_sel + p*32 + wid*KK;
    for (int k = 0; k < KK; ++k) {
        float m = v[0];
        #pragma unroll
        for (int q = 1; q < 22; ++q) m = fmaxf(m, v[q]);
        #pragma unroll
        for (int off = 16; off > 0; off >>= 1)
            m = fmaxf(m, __shfl_xor_sync(0xffffffffu, m, off));
        // remove exactly one occurrence (lowest lane, first slot)
        bool mine = false;
        #pragma unroll
        for (int q = 0; q < 22; ++q) mine |= (v[q] == m);
        unsigned ball = __ballot_sync(0xffffffffu, mine);
        if (lane == (__ffs(ball) - 1)) {
            bool done = false;
            #pragma unroll
            for (int q = 0; q < 22; ++q)
                if (!done && v[q] == m) { v[q] = -CUDART_INF_F; done = true; }
        }
        if (lane == 0) outp[k] = wid ? -m : m;
    }
}

// ---------------------------------------------------------------------------
// Kernel B: per-row partition sums + top-k softmax values.
// One lane owns one row i: a = Y1[n,s,i]+b1; S = sum_j exp2(a*u_j - m2).
// Output mapping (torch .view semantics): within a pair, output flat index
// L = kq*704 + j holds val(row = L>>4, rank = L&15). Row i's 16 rank-values
// occupy the contiguous range [16i, 16i+16); 704 = 44*16 so no kq straddle.
// ---------------------------------------------------------------------------
__global__ __launch_bounds__(64)
void attn_kernel(const float* __restrict__ b1p,
                 const float* __restrict__ b2p,
                 float* __restrict__ out) {
    __shared__ float4 u4[HW/4];
    __shared__ float  selU[32];
    const int blk   = blockIdx.x;
    const int p     = blk / 11;
    const int chunk = blk % 11;           // 64-row chunk within the pair
    const int n = p / SM1, s = p % SM1;
    const int tid = threadIdx.x;
    const float b1 = *b1p, b2 = *b2p;

    float* u = reinterpret_cast<float*>(u4);
    for (int j = tid; j < HW; j += 64)
        u[j] = (g_Y2[(n*SSZ + s + 1)*HW + j] + b2) * LOG2E;
    if (tid < 32) selU[tid] = g_sel[p*32 + tid];
    __syncthreads();

    const float umax = selU[0], umin = selU[16];
    const int   i  = chunk*64 + tid;                  // row in [0, 704)
    const float a  = g_Y1[(n*SSZ + s)*HW + i] + b1;
    const bool  pos = (a > 0.f);
    const float m2 = a * (pos ? umax : umin);         // max logit (log2 domain)

    float acc0 = 0.f, acc1 = 0.f, acc2 = 0.f, acc3 = 0.f;
    #pragma unroll 4
    for (int j = 0; j < HW/4; ++j) {
        float4 uu = u4[j];                            // broadcast LDS.128
        acc0 += ex2f(fmaf(a, uu.x, -m2));
        acc1 += ex2f(fmaf(a, uu.y, -m2));
        acc2 += ex2f(fmaf(a, uu.z, -m2));
        acc3 += ex2f(fmaf(a, uu.w, -m2));
    }
    const float inv = 1.0f / ((acc0 + acc1) + (acc2 + acc3));

    const float* selp = pos ? selU : (selU + KK);
    float vals[KK];
    #pragma unroll
    for (int k = 0; k < KK; ++k)
        vals[k] = ex2f(fmaf(a, selp[k], -m2)) * inv;

    const int Lbase = i * KK;            // 16*i
    const int kq    = Lbase / HW;        // = i / 44
    const int j0    = Lbase % HW;
    float* op = out + (((size_t)(n*KK + kq))*SM1 + s)*HW + j0;
    float4* op4 = reinterpret_cast<float4*>(op);
    const float4* v4 = reinterpret_cast<const float4*>(vals);
    #pragma unroll
    for (int q = 0; q < 4; ++q)
        op4[q] = v4[q];
}

extern "C" void kernel_launch(void* const* d_in, const int* in_sizes, int n_in,
                              void* d_out, int out_size) {
    const float* x  = (const float*)d_in[0];
    const float* w1 = (const float*)d_in[1];
    const float* b1 = (const float*)d_in[2];
    const float* w2 = (const float*)d_in[3];
    const float* b2 = (const float*)d_in[4];
    float* out = (float*)d_out;

    conv_kernel<<<NPIX/256, 512>>>(x, w1, w2);
    sel_kernel<<<NP, 64>>>(b2);
    attn_kernel<<<NP*11, 64>>>(b1, b2, out);
}

// round 5
// speedup vs baseline: 1.7057x; 1.1882x over previous
#include <cuda_runtime.h>
#include <math_constants.h>

// Problem shape (fixed by the dataset):
// x: (4, 128, 31, 32, 22) f32; w1,w2: (128,); b1,b2 scalars; top_k = 16
// out: (4, 16, 30, 32, 22) f32
#define NB   4
#define CC   128
#define SSZ  31
#define HW   704      // 32*22
#define SM1  30       // SSZ-1
#define NP   (NB*SM1) // 120 frame pairs
#define KK   16
#define NPIX (NB*SSZ*HW)   // 87296
#define FRM  (SSZ*HW)      // 21824 (elements per (n,c) channel slab; % 4 == 0)
#define LOG2E 1.4426950408889634f

// Scratch (allocation-free rule: __device__ globals)
__device__ float g_Y1[NPIX];   // dot(x, w1) per pixel, no bias
__device__ float g_Y2[NPIX];   // dot(x, w2) per pixel, no bias
__device__ float g_sel[NP*32]; // per pair: [0..15] top16 of u desc, [16..31] bot16 asc

__device__ __forceinline__ float ex2f(float x) {
    float y;
    asm("ex2.approx.ftz.f32 %0, %1;" : "=f"(y) : "f"(x));
    return y;
}

// ---------------------------------------------------------------------------
// Kernel A v3: 1x1 conv (C->1) for both weight vectors, one pass over x.
// Thread = (pixel-quad, 32-channel slice). float4 loads -> 4x bytes-in-flight
// per LDG vs v2. Block 256 = 64 quads x 4 channel groups; smem combine.
// ---------------------------------------------------------------------------
__global__ __launch_bounds__(256)
void conv_kernel(const float* __restrict__ x,
                 const float* __restrict__ w1,
                 const float* __restrict__ w2) {
    __shared__ float  sw1[CC], sw2[CC];
    __shared__ float4 pa[3][64], pb[3][64];
    const int tid = threadIdx.x;
    const int ql  = tid & 63;       // quad lane within block
    const int grp = tid >> 6;       // channel group 0..3
    if (tid < CC) sw1[tid] = w1[tid];
    else          sw2[tid - CC] = w2[tid - CC];

    const int Q = blockIdx.x * 64 + ql;   // quad id, < 21824
    const int t = Q * 4;                  // flat pixel id (n, s, hw), 16B aligned
    const int n = t / FRM;                // quads never straddle n (FRM % 4 == 0)
    // addr of (n, c, s, i) = t + (n*(CC-1) + c) * FRM
    const float* xp  = x + (size_t)(n*(CC-1) + grp*32) * FRM + t;
    const float* pw1 = sw1 + grp*32;
    const float* pw2 = sw2 + grp*32;
    __syncthreads();

    float4 a1 = make_float4(0.f,0.f,0.f,0.f);
    float4 a2 = make_float4(0.f,0.f,0.f,0.f);
    #pragma unroll 8
    for (int c = 0; c < 32; ++c) {
        float4 v = *reinterpret_cast<const float4*>(xp + (size_t)c * FRM);
        float u1 = pw1[c], u2 = pw2[c];
        a1.x = fmaf(v.x, u1, a1.x); a1.y = fmaf(v.y, u1, a1.y);
        a1.z = fmaf(v.z, u1, a1.z); a1.w = fmaf(v.w, u1, a1.w);
        a2.x = fmaf(v.x, u2, a2.x); a2.y = fmaf(v.y, u2, a2.y);
        a2.z = fmaf(v.z, u2, a2.z); a2.w = fmaf(v.w, u2, a2.w);
    }
    if (grp) { pa[grp-1][ql] = a1; pb[grp-1][ql] = a2; }
    __syncthreads();
    if (grp == 0) {
        #pragma unroll
        for (int g = 0; g < 3; ++g) {
            float4 u = pa[g][ql], v = pb[g][ql];
            a1.x += u.x; a1.y += u.y; a1.z += u.z; a1.w += u.w;
            a2.x += v.x; a2.y += v.y; a2.z += v.z; a2.w += v.w;
        }
        *reinterpret_cast<float4*>(g_Y1 + t) = a1;
        *reinterpret_cast<float4*>(g_Y2 + t) = a2;
    }
}

// ---------------------------------------------------------------------------
// Kernel C: per pair, top16 (desc) and bottom16 (asc) of
//           u_j = (Y2[n, s+1, j] + b2) * log2e.
// Block = 64 threads: warp 0 -> top16, warp 1 -> bottom16 (negated max-sel).
// ---------------------------------------------------------------------------
__global__ __launch_bounds__(64)
void sel_kernel(const float* __restrict__ b2p) {
    const int p    = blockIdx.x;
    const int n    = p / SM1, s = p % SM1;
    const int lane = threadIdx.x & 31;
    const int wid  = threadIdx.x >> 5;        // 0: max, 1: min
    const float b2 = *b2p;
    const float* Y2 = g_Y2 + (n*SSZ + s + 1)*HW;

    float v[22];
    #pragma unroll
    for (int q = 0; q < 22; ++q)
        v[q] = (Y2[q*32 + lane] + b2) * LOG2E;
    if (wid) {
        #pragma unroll
        for (int q = 0; q < 22; ++q) v[q] = -v[q];
    }

    float* outp = g_sel + p*32 + wid*KK;
    for (int k = 0; k < KK; ++k) {
        float m = v[0];
        #pragma unroll
        for (int q = 1; q < 22; ++q) m = fmaxf(m, v[q]);
        #pragma unroll
        for (int off = 16; off > 0; off >>= 1)
            m = fmaxf(m, __shfl_xor_sync(0xffffffffu, m, off));
        bool mine = false;
        #pragma unroll
        for (int q = 0; q < 22; ++q) mine |= (v[q] == m);
        unsigned ball = __ballot_sync(0xffffffffu, mine);
        if (lane == (__ffs(ball) - 1)) {
            bool done = false;
            #pragma unroll
            for (int q = 0; q < 22; ++q)
                if (!done && v[q] == m) { v[q] = -CUDART_INF_F; done = true; }
        }
        if (lane == 0) outp[k] = wid ? -m : m;
    }
}

// ---------------------------------------------------------------------------
// Kernel B: per-row partition sums + top-k softmax values (MUFU-bound floor).
// One lane owns one row i: a = Y1[n,s,i]+b1; S = sum_j exp2(a*u_j - m2).
// Output mapping (torch .view semantics): row i's 16 rank-values occupy the
// contiguous range [16i, 16i+16) of the pair's flat output; 704 = 44*16 so
// the range never straddles a kq slice: kq = i/44, j0 = (16i) % 704.
// ---------------------------------------------------------------------------
__global__ __launch_bounds__(64)
void attn_kernel(const float* __restrict__ b1p,
                 const float* __restrict__ b2p,
                 float* __restrict__ out) {
    __shared__ float4 u4[HW/4];
    __shared__ float  selU[32];
    const int blk   = blockIdx.x;
    const int p     = blk / 11;
    const int chunk = blk % 11;           // 64-row chunk within the pair
    const int n = p / SM1, s = p % SM1;
    const int tid = threadIdx.x;
    const float b1 = *b1p, b2 = *b2p;

    float* u = reinterpret_cast<float*>(u4);
    for (int j = tid; j < HW; j += 64)
        u[j] = (g_Y2[(n*SSZ + s + 1)*HW + j] + b2) * LOG2E;
    if (tid < 32) selU[tid] = g_sel[p*32 + tid];
    __syncthreads();

    const float umax = selU[0], umin = selU[16];
    const int   i  = chunk*64 + tid;                  // row in [0, 704)
    const float a  = g_Y1[(n*SSZ + s)*HW + i] + b1;
    const bool  pos = (a > 0.f);
    const float m2 = a * (pos ? umax : umin);         // max logit (log2 domain)

    float acc0 = 0.f, acc1 = 0.f, acc2 = 0.f, acc3 = 0.f;
    #pragma unroll 4
    for (int j = 0; j < HW/4; ++j) {
        float4 uu = u4[j];                            // broadcast LDS.128
        acc0 += ex2f(fmaf(a, uu.x, -m2));
        acc1 += ex2f(fmaf(a, uu.y, -m2));
        acc2 += ex2f(fmaf(a, uu.z, -m2));
        acc3 += ex2f(fmaf(a, uu.w, -m2));
    }
    const float inv = 1.0f / ((acc0 + acc1) + (acc2 + acc3));

    const float* selp = pos ? selU : (selU + KK);
    float vals[KK];
    #pragma unroll
    for (int k = 0; k < KK; ++k)
        vals[k] = ex2f(fmaf(a, selp[k], -m2)) * inv;

    const int Lbase = i * KK;            // 16*i
    const int kq    = Lbase / HW;        // = i / 44
    const int j0    = Lbase % HW;
    float* op = out + (((size_t)(n*KK + kq))*SM1 + s)*HW + j0;
    float4* op4 = reinterpret_cast<float4*>(op);
    const float4* v4 = reinterpret_cast<const float4*>(vals);
    #pragma unroll
    for (int q = 0; q < 4; ++q)
        op4[q] = v4[q];
}

extern "C" void kernel_launch(void* const* d_in, const int* in_sizes, int n_in,
                              void* d_out, int out_size) {
    const float* x  = (const float*)d_in[0];
    const float* w1 = (const float*)d_in[1];
    const float* b1 = (const float*)d_in[2];
    const float* w2 = (const float*)d_in[3];
    const float* b2 = (const float*)d_in[4];
    float* out = (float*)d_out;

    conv_kernel<<<(NPIX/4)/64, 256>>>(x, w1, w2);   // 341 blocks
    sel_kernel<<<NP, 64>>>(b2);
    attn_kernel<<<NP*11, 64>>>(b1, b2, out);
}